// round 5
// baseline (speedup 1.0000x reference)
#include <cuda_runtime.h>
#include <cuda_bf16.h>
#include <cstdint>
#include <cstddef>

// ---------------- problem constants ----------------
#define DD   768
#define MTOK 16
#define SS   1024
#define BB   16
#define TT   (SS + MTOK)   // 1040
#define TP   1152          // padded kv len
#define NQ   (BB * SS)     // 16384
#define NKV  (BB * TT)     // 16640
#define SCALE 0.036084391824351615f

// ---------------- scratch (device globals) ----------------
__device__ __align__(256) __nv_bfloat16 g_kvhi[(size_t)NKV * DD];
__device__ __align__(256) __nv_bfloat16 g_kvlo[(size_t)NKV * DD];
__device__ __align__(256) __nv_bfloat16 g_qhi [(size_t)NQ  * DD];
__device__ __align__(256) __nv_bfloat16 g_qlo [(size_t)NQ  * DD];
__device__ __align__(256) __nv_bfloat16 g_khi [(size_t)NKV * DD];
__device__ __align__(256) __nv_bfloat16 g_klo [(size_t)NKV * DD];
__device__ __align__(256) __nv_bfloat16 g_vthi[(size_t)BB * DD * TP];
__device__ __align__(256) __nv_bfloat16 g_vtlo[(size_t)BB * DD * TP];
__device__ __align__(256) float         g_sc  [(size_t)BB * SS * TP];
__device__ __align__(256) __nv_bfloat16 g_phi [(size_t)BB * SS * TP];
__device__ __align__(256) __nv_bfloat16 g_plo [(size_t)BB * SS * TP];
__device__ __align__(256) __nv_bfloat16 g_hhi [(size_t)NQ  * DD];
__device__ __align__(256) __nv_bfloat16 g_hlo [(size_t)NQ  * DD];
__device__ __align__(256) __nv_bfloat16 g_whi [4][(size_t)DD * DD];
__device__ __align__(256) __nv_bfloat16 g_wlo [4][(size_t)DD * DD];

// ---------------- helpers ----------------
__device__ __forceinline__ void bsplit(float f, __nv_bfloat16& h, __nv_bfloat16& l) {
    h = __float2bfloat16(f);
    l = __float2bfloat16(f - __bfloat162float(h));
}
__device__ __forceinline__ uint32_t smem_u32(const void* p) {
    uint32_t a;
    asm("{ .reg .u64 t; cvta.to.shared.u64 t, %1; cvt.u32.u64 %0, t; }" : "=r"(a) : "l"(p));
    return a;
}
__device__ __forceinline__ void cp16(uint32_t dst, const void* src) {
    asm volatile("cp.async.cg.shared.global [%0], [%1], 16;" :: "r"(dst), "l"(src));
}
__device__ __forceinline__ void cp_commit() {
    asm volatile("cp.async.commit_group;" ::: "memory");
}
template <int N>
__device__ __forceinline__ void cp_wait() {
    asm volatile("cp.async.wait_group %0;" :: "n"(N) : "memory");
}
__device__ __forceinline__ void ldm4(uint32_t* r, uint32_t addr) {
    asm volatile("ldmatrix.sync.aligned.m8n8.x4.shared.b16 {%0,%1,%2,%3},[%4];"
                 : "=r"(r[0]), "=r"(r[1]), "=r"(r[2]), "=r"(r[3]) : "r"(addr));
}
__device__ __forceinline__ void mma16816(float* c, const uint32_t* a, const uint32_t* b) {
    asm volatile("mma.sync.aligned.m16n8k16.row.col.f32.bf16.bf16.f32 "
                 "{%0,%1,%2,%3},{%4,%5,%6,%7},{%8,%9},{%0,%1,%2,%3};"
                 : "+f"(c[0]), "+f"(c[1]), "+f"(c[2]), "+f"(c[3])
                 : "r"(a[0]), "r"(a[1]), "r"(a[2]), "r"(a[3]), "r"(b[0]), "r"(b[1]));
}

// ---------------- elementwise prep ----------------
__global__ void build_kv(const float4* __restrict__ x, const float4* __restrict__ mem) {
    const int n4 = NKV * (DD / 4);
    int i = blockIdx.x * 256 + threadIdx.x;
    if (i >= n4) return;
    int d4  = i % (DD / 4);
    int row = i / (DD / 4);
    int b = row / TT, t = row % TT;
    float4 v = (t < SS) ? x[(size_t)(b * SS + t) * (DD / 4) + d4]
                        : mem[(size_t)(t - SS) * (DD / 4) + d4];
    union { __nv_bfloat16 bb[4]; uint2 u; } H, L;
    bsplit(v.x, H.bb[0], L.bb[0]);
    bsplit(v.y, H.bb[1], L.bb[1]);
    bsplit(v.z, H.bb[2], L.bb[2]);
    bsplit(v.w, H.bb[3], L.bb[3]);
    ((uint2*)g_kvhi)[i] = H.u;
    ((uint2*)g_kvlo)[i] = L.u;
}

// split all 4 weight matrices in one launch
__global__ void split_all(const float4* __restrict__ w0, const float4* __restrict__ w1,
                          const float4* __restrict__ w2, const float4* __restrict__ w3) {
    const int w4 = DD * DD / 4;
    int i = blockIdx.x * 256 + threadIdx.x;
    if (i >= 4 * w4) return;
    int wsel = i / w4;
    int j    = i % w4;
    const float4* src = (wsel == 0) ? w0 : (wsel == 1) ? w1 : (wsel == 2) ? w2 : w3;
    float4 v = src[j];
    union { __nv_bfloat16 bb[4]; uint2 u; } H, L;
    bsplit(v.x, H.bb[0], L.bb[0]);
    bsplit(v.y, H.bb[1], L.bb[1]);
    bsplit(v.z, H.bb[2], L.bb[2]);
    bsplit(v.w, H.bb[3], L.bb[3]);
    ((uint2*)g_whi[wsel])[j] = H.u;
    ((uint2*)g_wlo[wsel])[j] = L.u;
}

// ---------------- HMMA split-bf16 GEMM ----------------
// C[M,N] = alpha*(A*B^T) (+bias) (+mask). A,B as hi/lo bf16 pairs, K-major.
// Block 256x128, BK=32, 256 threads (8 warps, 4x2), warp tile 64x64.
// hi|lo packed in 128B XOR-swizzled rows. 3-stage cp.async, 1 sync/chunk.

#define AST 32768                  // A tile bytes per stage (256 rows x 128B)
#define BST 16384                  // B tile bytes per stage (128 rows x 128B)
#define STAGE (AST + BST)          // 49152
#define GSMEM (3 * STAGE)          // 147456

__global__ void __launch_bounds__(256, 1)
gemm3(const __nv_bfloat16* __restrict__ Ahi, const __nv_bfloat16* __restrict__ Alo,
      long long sA, int ldA, int mrealA,
      const __nv_bfloat16* __restrict__ Bhi, const __nv_bfloat16* __restrict__ Blo,
      long long sB, int ldB, int nrealB,
      int K, float alpha,
      const float* __restrict__ bias, int bias_mode,   // 0 none, 1 over N, 2 over M
      const float* __restrict__ mask, int mask_ld, int mask_n,
      float* __restrict__ Cf, __nv_bfloat16* __restrict__ Chi, __nv_bfloat16* __restrict__ Clo,
      long long sC, int ldC)
{
    extern __shared__ char smem[];
    const uint32_t sb = smem_u32(smem);
    const int tid  = threadIdx.x;
    const int lane = tid & 31;
    const int warp = tid >> 5;
    const int wm = warp >> 1;          // 0..3 (64-row slabs)
    const int wn = warp & 1;           // 0..1 (64-col slabs)

    const int m0 = blockIdx.y * 256, n0 = blockIdx.x * 128;
    const __nv_bfloat16* pAh = Ahi + (size_t)blockIdx.z * sA;
    const __nv_bfloat16* pAl = Alo + (size_t)blockIdx.z * sA;
    const __nv_bfloat16* pBh = Bhi + (size_t)blockIdx.z * sB;
    const __nv_bfloat16* pBl = Blo + (size_t)blockIdx.z * sB;

    // ---- cp.async mapping ----
    // A: thread owns row tid (0..255); chunks 0-3 hi k0..31, 4-7 lo k0..31
    int garow = m0 + tid; if (garow >= mrealA) garow = mrealA - 1;
    const __nv_bfloat16* srcAh = pAh + (size_t)garow * ldA;
    const __nv_bfloat16* srcAl = pAl + (size_t)garow * ldA;
    uint32_t dstA[8];
    #pragma unroll
    for (int c = 0; c < 8; c++)
        dstA[c] = sb + (uint32_t)tid * 128u + (uint32_t)((c ^ (tid & 7)) * 16);

    // B: row = tid>>1 (0..127); half selects hi (chunks 0-3) or lo (4-7)
    const int brow = tid >> 1, bhalf = tid & 1;
    int gbrow = n0 + brow; if (gbrow >= nrealB) gbrow = nrealB - 1;
    const __nv_bfloat16* srcB = (bhalf ? pBl : pBh) + (size_t)gbrow * ldB;
    uint32_t dstB[4];
    #pragma unroll
    for (int j = 0; j < 4; j++)
        dstB[j] = sb + AST + (uint32_t)brow * 128u
                + (uint32_t)((((bhalf << 2) + j) ^ (brow & 7)) * 16);

    const int nchunk = K >> 5;

    auto prefetch = [&](int c, int stg) {
        const uint32_t so = (uint32_t)stg * STAGE;
        const int k0 = c << 5;
        #pragma unroll
        for (int cc = 0; cc < 4; cc++) cp16(dstA[cc]     + so, srcAh + k0 + cc * 8);
        #pragma unroll
        for (int cc = 0; cc < 4; cc++) cp16(dstA[cc + 4] + so, srcAl + k0 + cc * 8);
        #pragma unroll
        for (int j = 0; j < 4; j++)    cp16(dstB[j]      + so, srcB  + k0 + j * 8);
    };

    float acc[4][8][4];
    #pragma unroll
    for (int i = 0; i < 4; i++)
        #pragma unroll
        for (int j = 0; j < 8; j++)
            #pragma unroll
            for (int q = 0; q < 4; q++) acc[i][j][q] = 0.0f;

    // ---- ldmatrix lane constants ----
    const uint32_t band  = (uint32_t)(lane & 7);
    const uint32_t a_hi  = (uint32_t)(lane >> 4);        // 0/1 k-subchunk for A
    uint32_t arowt[4];
    #pragma unroll
    for (int mt = 0; mt < 4; mt++)
        arowt[mt] = (uint32_t)(wm * 64 + mt * 16 + (lane & 15)) * 128u;
    const uint32_t b_off = (uint32_t)(((lane >> 4) & 1) * 8 + (lane & 7));
    const uint32_t b_hi  = (uint32_t)((lane >> 3) & 1);

    prefetch(0, 0); cp_commit();
    if (nchunk > 1) prefetch(1, 1);
    cp_commit();

    for (int c = 0; c < nchunk; c++) {
        cp_wait<1>();
        __syncthreads();
        if (c + 2 < nchunk) prefetch(c + 2, (c + 2) % 3);   // FIX: stage = (c+2) mod 3
        cp_commit();

        const uint32_t Ab = sb + (uint32_t)(c % 3) * STAGE;
        const uint32_t Bb = Ab + AST;

        #pragma unroll
        for (int ks = 0; ks < 2; ks++) {
            uint32_t ah[4][4], al[4][4];
            const uint32_t ch = (uint32_t)(ks * 2) + a_hi;
            #pragma unroll
            for (int mt = 0; mt < 4; mt++) {
                ldm4(ah[mt], Ab + arowt[mt] + ((ch    ) ^ band) * 16);
                ldm4(al[mt], Ab + arowt[mt] + ((ch + 4) ^ band) * 16);
            }
            const uint32_t cb = (uint32_t)(ks * 2) + b_hi;
            #pragma unroll
            for (int ntp = 0; ntp < 4; ntp++) {
                uint32_t bh[4], bl[4];
                const uint32_t brt = (uint32_t)(wn * 64 + ntp * 16) * 128u + b_off * 128u;
                ldm4(bh, Bb + brt + ((cb    ) ^ band) * 16);
                ldm4(bl, Bb + brt + ((cb + 4) ^ band) * 16);
                #pragma unroll
                for (int mt = 0; mt < 4; mt++) {
                    mma16816(acc[mt][ntp * 2    ], ah[mt], bh);
                    mma16816(acc[mt][ntp * 2    ], ah[mt], bl);
                    mma16816(acc[mt][ntp * 2    ], al[mt], bh);
                    mma16816(acc[mt][ntp * 2 + 1], ah[mt], bh + 2);
                    mma16816(acc[mt][ntp * 2 + 1], ah[mt], bl + 2);
                    mma16816(acc[mt][ntp * 2 + 1], al[mt], bh + 2);
                }
            }
        }
    }

    // ---- epilogue ----
    float* pC = Cf ? (Cf + (size_t)blockIdx.z * sC) : (float*)0;
    __nv_bfloat16* pCh = Chi ? (Chi + (size_t)blockIdx.z * sC) : (__nv_bfloat16*)0;
    __nv_bfloat16* pCl = Clo ? (Clo + (size_t)blockIdx.z * sC) : (__nv_bfloat16*)0;

    #pragma unroll
    for (int mt = 0; mt < 4; mt++) {
        const int row0 = m0 + wm * 64 + mt * 16 + (lane >> 2);
        #pragma unroll
        for (int nt = 0; nt < 8; nt++) {
            const int col = n0 + wn * 64 + nt * 8 + (lane & 3) * 2;
            #pragma unroll
            for (int half = 0; half < 2; half++) {
                const int row = row0 + half * 8;
                float v0 = acc[mt][nt][half * 2    ] * alpha;
                float v1 = acc[mt][nt][half * 2 + 1] * alpha;
                if (bias_mode == 1) {
                    float2 bv = *(const float2*)(bias + col);
                    v0 += bv.x; v1 += bv.y;
                } else if (bias_mode == 2) {
                    float bm = bias[row];
                    v0 += bm; v1 += bm;
                }
                if (mask && col < mask_n) {
                    float2 mv = *(const float2*)(mask + (size_t)row * mask_ld + col);
                    v0 += mv.x; v1 += mv.y;
                }
                if (pC) {
                    float2 ov; ov.x = v0; ov.y = v1;
                    *(float2*)(pC + (size_t)row * ldC + col) = ov;
                } else {
                    __nv_bfloat16 h0, l0, h1, l1;
                    bsplit(v0, h0, l0);
                    bsplit(v1, h1, l1);
                    union { __nv_bfloat16 bb[2]; uint32_t u; } H, L;
                    H.bb[0] = h0; H.bb[1] = h1;
                    L.bb[0] = l0; L.bb[1] = l1;
                    *(uint32_t*)(pCh + (size_t)row * ldC + col) = H.u;
                    *(uint32_t*)(pCl + (size_t)row * ldC + col) = L.u;
                }
            }
        }
    }
}

// ---------------- softmax ----------------
__device__ __forceinline__ float wmax(float v) {
    #pragma unroll
    for (int o = 16; o > 0; o >>= 1) v = fmaxf(v, __shfl_xor_sync(0xFFFFFFFFu, v, o));
    return v;
}
__device__ __forceinline__ float wsum(float v) {
    #pragma unroll
    for (int o = 16; o > 0; o >>= 1) v += __shfl_xor_sync(0xFFFFFFFFu, v, o);
    return v;
}

__global__ void __launch_bounds__(256)
softmax_split(const float* __restrict__ SC, __nv_bfloat16* __restrict__ Phi,
              __nv_bfloat16* __restrict__ Plo)
{
    const size_t base = (size_t)blockIdx.x * TP;
    const float* rrow = SC + base;
    const int tid = threadIdx.x, lane = tid & 31, warp = tid >> 5;
    __shared__ float red[8];

    float v[5];
    float mx = -1e30f;
    #pragma unroll
    for (int i = 0; i < 5; i++) {
        int t = tid + i * 256;
        if (t < TT) { float x = rrow[t]; v[i] = x; mx = fmaxf(mx, x); }
        else v[i] = -1e30f;
    }
    mx = wmax(mx);
    if (lane == 0) red[warp] = mx;
    __syncthreads();
    if (warp == 0) {
        float x = (lane < 8) ? red[lane] : -1e30f;
        x = wmax(x);
        if (lane == 0) red[0] = x;
    }
    __syncthreads();
    mx = red[0];
    __syncthreads();

    float sum = 0.0f;
    #pragma unroll
    for (int i = 0; i < 5; i++) {
        int t = tid + i * 256;
        if (t < TT) { float e = expf(v[i] - mx); v[i] = e; sum += e; }
    }
    sum = wsum(sum);
    if (lane == 0) red[warp] = sum;
    __syncthreads();
    if (warp == 0) {
        float x = (lane < 8) ? red[lane] : 0.0f;
        x = wsum(x);
        if (lane == 0) red[0] = x;
    }
    __syncthreads();
    const float inv = 1.0f / red[0];

    #pragma unroll
    for (int i = 0; i < 5; i++) {
        int t = tid + i * 256;
        if (t < TT) {
            float p = v[i] * inv;
            __nv_bfloat16 hh, ll;
            bsplit(p, hh, ll);
            Phi[base + t] = hh;
            Plo[base + t] = ll;
        } else if (t < TP) {
            Phi[base + t] = __float2bfloat16(0.0f);
            Plo[base + t] = __float2bfloat16(0.0f);
        }
    }
}

// ---------------- launch ----------------
extern "C" void kernel_launch(void* const* d_in, const int* in_sizes, int n_in,
                              void* d_out, int out_size)
{
    const float* x    = (const float*)d_in[0];
    const float* mask = (const float*)d_in[1];
    const float* mem  = (const float*)d_in[2];
    const float* wq   = (const float*)d_in[3];
    const float* bq   = (const float*)d_in[4];
    const float* wk   = (const float*)d_in[5];
    const float* bk   = (const float*)d_in[6];
    const float* wv   = (const float*)d_in[7];
    const float* bv   = (const float*)d_in[8];
    const float* wo   = (const float*)d_in[9];
    const float* bo   = (const float*)d_in[10];
    float* out = (float*)d_out;

    __nv_bfloat16 *kvhi, *kvlo, *qhi, *qlo, *khi, *klo, *vthi, *vtlo, *phi, *plo, *hhi, *hlo;
    __nv_bfloat16 (*whi)[(size_t)DD * DD];
    __nv_bfloat16 (*wlo)[(size_t)DD * DD];
    float* sc;
    cudaGetSymbolAddress((void**)&kvhi, g_kvhi);
    cudaGetSymbolAddress((void**)&kvlo, g_kvlo);
    cudaGetSymbolAddress((void**)&qhi,  g_qhi);
    cudaGetSymbolAddress((void**)&qlo,  g_qlo);
    cudaGetSymbolAddress((void**)&khi,  g_khi);
    cudaGetSymbolAddress((void**)&klo,  g_klo);
    cudaGetSymbolAddress((void**)&vthi, g_vthi);
    cudaGetSymbolAddress((void**)&vtlo, g_vtlo);
    cudaGetSymbolAddress((void**)&sc,   g_sc);
    cudaGetSymbolAddress((void**)&phi,  g_phi);
    cudaGetSymbolAddress((void**)&plo,  g_plo);
    cudaGetSymbolAddress((void**)&hhi,  g_hhi);
    cudaGetSymbolAddress((void**)&hlo,  g_hlo);
    cudaGetSymbolAddress((void**)&whi,  g_whi);
    cudaGetSymbolAddress((void**)&wlo,  g_wlo);

    cudaFuncSetAttribute(gemm3, cudaFuncAttributeMaxDynamicSharedMemorySize, GSMEM);

    // 0: concat + split kv input
    {
        int n4 = NKV * (DD / 4);
        build_kv<<<(n4 + 255) / 256, 256>>>((const float4*)x, (const float4*)mem);
    }
    // 1: split all weights (one launch)
    {
        int tot = 4 * (DD * DD / 4);
        split_all<<<(tot + 255) / 256, 256>>>((const float4*)wq, (const float4*)wk,
                                              (const float4*)wv, (const float4*)wo);
    }

    // 2: Q = x * wq^T + bq (batched; A rows skip memory tokens)
    gemm3<<<dim3(DD / 128, SS / 256, BB), 256, GSMEM>>>(
        kvhi, kvlo, (long long)TT * DD, DD, SS,
        whi[0], wlo[0], 0, DD, DD,
        DD, 1.0f, bq, 1, nullptr, 0, 0,
        nullptr, qhi, qlo, (long long)SS * DD, DD);

    // 3: K = kv * wk^T + bk
    gemm3<<<dim3(DD / 128, NKV / 256, 1), 256, GSMEM>>>(
        kvhi, kvlo, 0, DD, NKV,
        whi[1], wlo[1], 0, DD, DD,
        DD, 1.0f, bk, 1, nullptr, 0, 0,
        nullptr, khi, klo, 0, DD);

    // 4: Vt[b] = wv * kv[b]^T + bv(rows)   [768 x TP]
    gemm3<<<dim3(TP / 128, DD / 256, BB), 256, GSMEM>>>(
        whi[2], wlo[2], 0, DD, DD,
        kvhi, kvlo, (long long)TT * DD, DD, TT,
        DD, 1.0f, bv, 2, nullptr, 0, 0,
        nullptr, vthi, vtlo, (long long)DD * TP, TP);

    // 5: scores[b] = SCALE * Q[b] K[b]^T + mask -> fp32   (ncu capture target)
    gemm3<<<dim3(TP / 128, SS / 256, BB), 256, GSMEM>>>(
        qhi, qlo, (long long)SS * DD, DD, SS,
        khi, klo, (long long)TT * DD, DD, TT,
        DD, SCALE, nullptr, 0, mask, TT, TT,
        sc, nullptr, nullptr, (long long)SS * TP, TP);

    // 6: softmax -> split P (pad cols zeroed)
    softmax_split<<<NQ, 256>>>(sc, phi, plo);

    // 7: H[b] = P[b] * Vt[b]^T
    gemm3<<<dim3(DD / 128, SS / 256, BB), 256, GSMEM>>>(
        phi, plo, (long long)SS * TP, TP, SS,
        vthi, vtlo, (long long)DD * TP, TP, DD,
        TP, 1.0f, nullptr, 0, nullptr, 0, 0,
        nullptr, hhi, hlo, (long long)SS * DD, DD);

    // 8: out = H * wo^T + bo -> fp32 d_out
    gemm3<<<dim3(DD / 128, NQ / 256, 1), 256, GSMEM>>>(
        hhi, hlo, 0, DD, NQ,
        whi[3], wlo[3], 0, DD, DD,
        DD, 1.0f, bo, 1, nullptr, 0, 0,
        out, nullptr, nullptr, 0, DD);
}

// round 6
// speedup vs baseline: 1.0175x; 1.0175x over previous
#include <cuda_runtime.h>
#include <cuda_bf16.h>
#include <cstdint>
#include <cstddef>

// ---------------- problem constants ----------------
#define DD   768
#define MTOK 16
#define SS   1024
#define BB   16
#define TT   (SS + MTOK)   // 1040
#define TP   1152          // padded kv len (array stride)
#define KPV  1056          // K extent for P*Vt GEMM (>= TT, mult of 32)
#define NQ   (BB * SS)     // 16384
#define NKV  (BB * TT)     // 16640
#define SCALE 0.036084391824351615f

// ---------------- scratch (device globals) ----------------
__device__ __align__(256) __nv_bfloat16 g_kvhi[(size_t)NKV * DD];
__device__ __align__(256) __nv_bfloat16 g_kvlo[(size_t)NKV * DD];
__device__ __align__(256) __nv_bfloat16 g_qhi [(size_t)NQ  * DD];
__device__ __align__(256) __nv_bfloat16 g_qlo [(size_t)NQ  * DD];
__device__ __align__(256) __nv_bfloat16 g_khi [(size_t)NKV * DD];
__device__ __align__(256) __nv_bfloat16 g_klo [(size_t)NKV * DD];
__device__ __align__(256) __nv_bfloat16 g_vthi[(size_t)BB * DD * TP];
__device__ __align__(256) __nv_bfloat16 g_vtlo[(size_t)BB * DD * TP];
__device__ __align__(256) float         g_sc  [(size_t)BB * SS * TP];
__device__ __align__(256) __nv_bfloat16 g_phi [(size_t)BB * SS * TP];
__device__ __align__(256) __nv_bfloat16 g_plo [(size_t)BB * SS * TP];
__device__ __align__(256) __nv_bfloat16 g_hhi [(size_t)NQ  * DD];
__device__ __align__(256) __nv_bfloat16 g_hlo [(size_t)NQ  * DD];
__device__ __align__(256) __nv_bfloat16 g_whi [4][(size_t)DD * DD];
__device__ __align__(256) __nv_bfloat16 g_wlo [4][(size_t)DD * DD];

// ---------------- helpers ----------------
__device__ __forceinline__ void bsplit(float f, __nv_bfloat16& h, __nv_bfloat16& l) {
    h = __float2bfloat16(f);
    l = __float2bfloat16(f - __bfloat162float(h));
}
__device__ __forceinline__ uint32_t smem_u32(const void* p) {
    uint32_t a;
    asm("{ .reg .u64 t; cvta.to.shared.u64 t, %1; cvt.u32.u64 %0, t; }" : "=r"(a) : "l"(p));
    return a;
}
__device__ __forceinline__ void cp16(uint32_t dst, const void* src) {
    asm volatile("cp.async.cg.shared.global [%0], [%1], 16;" :: "r"(dst), "l"(src));
}
__device__ __forceinline__ void cp_commit() {
    asm volatile("cp.async.commit_group;" ::: "memory");
}
template <int N>
__device__ __forceinline__ void cp_wait() {
    asm volatile("cp.async.wait_group %0;" :: "n"(N) : "memory");
}
__device__ __forceinline__ void ldm4(uint32_t* r, uint32_t addr) {
    asm volatile("ldmatrix.sync.aligned.m8n8.x4.shared.b16 {%0,%1,%2,%3},[%4];"
                 : "=r"(r[0]), "=r"(r[1]), "=r"(r[2]), "=r"(r[3]) : "r"(addr));
}
__device__ __forceinline__ void mma16816(float* c, const uint32_t* a, const uint32_t* b) {
    asm volatile("mma.sync.aligned.m16n8k16.row.col.f32.bf16.bf16.f32 "
                 "{%0,%1,%2,%3},{%4,%5,%6,%7},{%8,%9},{%0,%1,%2,%3};"
                 : "+f"(c[0]), "+f"(c[1]), "+f"(c[2]), "+f"(c[3])
                 : "r"(a[0]), "r"(a[1]), "r"(a[2]), "r"(a[3]), "r"(b[0]), "r"(b[1]));
}

// ---------------- elementwise prep ----------------
__global__ void build_kv(const float4* __restrict__ x, const float4* __restrict__ mem) {
    const int n4 = NKV * (DD / 4);
    int i = blockIdx.x * 256 + threadIdx.x;
    if (i >= n4) return;
    int d4  = i % (DD / 4);
    int row = i / (DD / 4);
    int b = row / TT, t = row % TT;
    float4 v = (t < SS) ? x[(size_t)(b * SS + t) * (DD / 4) + d4]
                        : mem[(size_t)(t - SS) * (DD / 4) + d4];
    union { __nv_bfloat16 bb[4]; uint2 u; } H, L;
    bsplit(v.x, H.bb[0], L.bb[0]);
    bsplit(v.y, H.bb[1], L.bb[1]);
    bsplit(v.z, H.bb[2], L.bb[2]);
    bsplit(v.w, H.bb[3], L.bb[3]);
    ((uint2*)g_kvhi)[i] = H.u;
    ((uint2*)g_kvlo)[i] = L.u;
}

__global__ void split_all(const float4* __restrict__ w0, const float4* __restrict__ w1,
                          const float4* __restrict__ w2, const float4* __restrict__ w3) {
    const int w4 = DD * DD / 4;
    int i = blockIdx.x * 256 + threadIdx.x;
    if (i >= 4 * w4) return;
    int wsel = i / w4;
    int j    = i % w4;
    const float4* src = (wsel == 0) ? w0 : (wsel == 1) ? w1 : (wsel == 2) ? w2 : w3;
    float4 v = src[j];
    union { __nv_bfloat16 bb[4]; uint2 u; } H, L;
    bsplit(v.x, H.bb[0], L.bb[0]);
    bsplit(v.y, H.bb[1], L.bb[1]);
    bsplit(v.z, H.bb[2], L.bb[2]);
    bsplit(v.w, H.bb[3], L.bb[3]);
    ((uint2*)g_whi[wsel])[j] = H.u;
    ((uint2*)g_wlo[wsel])[j] = L.u;
}

// ---------------- HMMA split-bf16 GEMM ----------------
// Block 256x128, BK=32, 256 threads (8 warps, 4x2), warp tile 64x64.
// MMA issue ordered by product (hh, hl, lh) so same-acc reuse distance = 8.

#define AST 32768
#define BST 16384
#define STAGE (AST + BST)          // 49152
#define GSMEM (3 * STAGE)          // 147456

__global__ void __launch_bounds__(256, 1)
gemm3(const __nv_bfloat16* __restrict__ Ahi, const __nv_bfloat16* __restrict__ Alo,
      long long sA, int ldA, int mrealA,
      const __nv_bfloat16* __restrict__ Bhi, const __nv_bfloat16* __restrict__ Blo,
      long long sB, int ldB, int nrealB,
      int K, float alpha,
      const float* __restrict__ bias, int bias_mode,
      const float* __restrict__ mask, int mask_ld, int mask_n,
      float* __restrict__ Cf, __nv_bfloat16* __restrict__ Chi, __nv_bfloat16* __restrict__ Clo,
      long long sC, int ldC)
{
    extern __shared__ char smem[];
    const uint32_t sb = smem_u32(smem);
    const int tid  = threadIdx.x;
    const int lane = tid & 31;
    const int warp = tid >> 5;
    const int wm = warp >> 1;
    const int wn = warp & 1;

    const int m0 = blockIdx.y * 256, n0 = blockIdx.x * 128;
    const __nv_bfloat16* pAh = Ahi + (size_t)blockIdx.z * sA;
    const __nv_bfloat16* pAl = Alo + (size_t)blockIdx.z * sA;
    const __nv_bfloat16* pBh = Bhi + (size_t)blockIdx.z * sB;
    const __nv_bfloat16* pBl = Blo + (size_t)blockIdx.z * sB;

    int garow = m0 + tid; if (garow >= mrealA) garow = mrealA - 1;
    const __nv_bfloat16* srcAh = pAh + (size_t)garow * ldA;
    const __nv_bfloat16* srcAl = pAl + (size_t)garow * ldA;
    uint32_t dstA[8];
    #pragma unroll
    for (int c = 0; c < 8; c++)
        dstA[c] = sb + (uint32_t)tid * 128u + (uint32_t)((c ^ (tid & 7)) * 16);

    const int brow = tid >> 1, bhalf = tid & 1;
    int gbrow = n0 + brow; if (gbrow >= nrealB) gbrow = nrealB - 1;
    const __nv_bfloat16* srcB = (bhalf ? pBl : pBh) + (size_t)gbrow * ldB;
    uint32_t dstB[4];
    #pragma unroll
    for (int j = 0; j < 4; j++)
        dstB[j] = sb + AST + (uint32_t)brow * 128u
                + (uint32_t)((((bhalf << 2) + j) ^ (brow & 7)) * 16);

    const int nchunk = K >> 5;

    auto prefetch = [&](int c, int stg) {
        const uint32_t so = (uint32_t)stg * STAGE;
        const int k0 = c << 5;
        #pragma unroll
        for (int cc = 0; cc < 4; cc++) cp16(dstA[cc]     + so, srcAh + k0 + cc * 8);
        #pragma unroll
        for (int cc = 0; cc < 4; cc++) cp16(dstA[cc + 4] + so, srcAl + k0 + cc * 8);
        #pragma unroll
        for (int j = 0; j < 4; j++)    cp16(dstB[j]      + so, srcB  + k0 + j * 8);
    };

    float acc[4][8][4];
    #pragma unroll
    for (int i = 0; i < 4; i++)
        #pragma unroll
        for (int j = 0; j < 8; j++)
            #pragma unroll
            for (int q = 0; q < 4; q++) acc[i][j][q] = 0.0f;

    const uint32_t band  = (uint32_t)(lane & 7);
    const uint32_t a_hi  = (uint32_t)(lane >> 4);
    uint32_t arowt[4];
    #pragma unroll
    for (int mt = 0; mt < 4; mt++)
        arowt[mt] = (uint32_t)(wm * 64 + mt * 16 + (lane & 15)) * 128u;
    const uint32_t b_off = (uint32_t)(((lane >> 4) & 1) * 8 + (lane & 7));
    const uint32_t b_hi  = (uint32_t)((lane >> 3) & 1);

    prefetch(0, 0); cp_commit();
    if (nchunk > 1) prefetch(1, 1);
    cp_commit();

    for (int c = 0; c < nchunk; c++) {
        cp_wait<1>();
        __syncthreads();
        if (c + 2 < nchunk) prefetch(c + 2, (c + 2) % 3);
        cp_commit();

        const uint32_t Ab = sb + (uint32_t)(c % 3) * STAGE;
        const uint32_t Bb = Ab + AST;

        #pragma unroll
        for (int ks = 0; ks < 2; ks++) {
            uint32_t ah[4][4], al[4][4];
            const uint32_t ch = (uint32_t)(ks * 2) + a_hi;
            #pragma unroll
            for (int mt = 0; mt < 4; mt++) {
                ldm4(ah[mt], Ab + arowt[mt] + ((ch    ) ^ band) * 16);
                ldm4(al[mt], Ab + arowt[mt] + ((ch + 4) ^ band) * 16);
            }
            const uint32_t cb = (uint32_t)(ks * 2) + b_hi;
            #pragma unroll
            for (int ntp = 0; ntp < 4; ntp++) {
                uint32_t bh[4], bl[4];
                const uint32_t brt = (uint32_t)(wn * 64 + ntp * 16) * 128u + b_off * 128u;
                ldm4(bh, Bb + brt + ((cb    ) ^ band) * 16);
                ldm4(bl, Bb + brt + ((cb + 4) ^ band) * 16);
                // product-major issue order: same-acc reuse distance = 8 MMAs
                #pragma unroll
                for (int mt = 0; mt < 4; mt++) {
                    mma16816(acc[mt][ntp * 2    ], ah[mt], bh);
                    mma16816(acc[mt][ntp * 2 + 1], ah[mt], bh + 2);
                }
                #pragma unroll
                for (int mt = 0; mt < 4; mt++) {
                    mma16816(acc[mt][ntp * 2    ], ah[mt], bl);
                    mma16816(acc[mt][ntp * 2 + 1], ah[mt], bl + 2);
                }
                #pragma unroll
                for (int mt = 0; mt < 4; mt++) {
                    mma16816(acc[mt][ntp * 2    ], al[mt], bh);
                    mma16816(acc[mt][ntp * 2 + 1], al[mt], bh + 2);
                }
            }
        }
    }

    // ---- epilogue ----
    float* pC = Cf ? (Cf + (size_t)blockIdx.z * sC) : (float*)0;
    __nv_bfloat16* pCh = Chi ? (Chi + (size_t)blockIdx.z * sC) : (__nv_bfloat16*)0;
    __nv_bfloat16* pCl = Clo ? (Clo + (size_t)blockIdx.z * sC) : (__nv_bfloat16*)0;

    #pragma unroll
    for (int mt = 0; mt < 4; mt++) {
        const int row0 = m0 + wm * 64 + mt * 16 + (lane >> 2);
        #pragma unroll
        for (int nt = 0; nt < 8; nt++) {
            const int col = n0 + wn * 64 + nt * 8 + (lane & 3) * 2;
            #pragma unroll
            for (int half = 0; half < 2; half++) {
                const int row = row0 + half * 8;
                float v0 = acc[mt][nt][half * 2    ] * alpha;
                float v1 = acc[mt][nt][half * 2 + 1] * alpha;
                if (bias_mode == 1) {
                    float2 bv = *(const float2*)(bias + col);
                    v0 += bv.x; v1 += bv.y;
                } else if (bias_mode == 2) {
                    float bm = bias[row];
                    v0 += bm; v1 += bm;
                }
                if (mask && col < mask_n) {
                    float2 mv = *(const float2*)(mask + (size_t)row * mask_ld + col);
                    v0 += mv.x; v1 += mv.y;
                }
                if (pC) {
                    float2 ov; ov.x = v0; ov.y = v1;
                    *(float2*)(pC + (size_t)row * ldC + col) = ov;
                } else {
                    __nv_bfloat16 h0, l0, h1, l1;
                    bsplit(v0, h0, l0);
                    bsplit(v1, h1, l1);
                    union { __nv_bfloat16 bb[2]; uint32_t u; } H, L;
                    H.bb[0] = h0; H.bb[1] = h1;
                    L.bb[0] = l0; L.bb[1] = l1;
                    *(uint32_t*)(pCh + (size_t)row * ldC + col) = H.u;
                    *(uint32_t*)(pCl + (size_t)row * ldC + col) = L.u;
                }
            }
        }
    }
}

// ---------------- softmax ----------------
__device__ __forceinline__ float wmax(float v) {
    #pragma unroll
    for (int o = 16; o > 0; o >>= 1) v = fmaxf(v, __shfl_xor_sync(0xFFFFFFFFu, v, o));
    return v;
}
__device__ __forceinline__ float wsum(float v) {
    #pragma unroll
    for (int o = 16; o > 0; o >>= 1) v += __shfl_xor_sync(0xFFFFFFFFu, v, o);
    return v;
}

__global__ void __launch_bounds__(256)
softmax_split(const float* __restrict__ SC, __nv_bfloat16* __restrict__ Phi,
              __nv_bfloat16* __restrict__ Plo)
{
    const size_t base = (size_t)blockIdx.x * TP;
    const float* rrow = SC + base;
    const int tid = threadIdx.x, lane = tid & 31, warp = tid >> 5;
    __shared__ float red[8];

    float v[5];
    float mx = -1e30f;
    #pragma unroll
    for (int i = 0; i < 5; i++) {
        int t = tid + i * 256;
        if (t < TT) { float x = rrow[t]; v[i] = x; mx = fmaxf(mx, x); }
        else v[i] = -1e30f;
    }
    mx = wmax(mx);
    if (lane == 0) red[warp] = mx;
    __syncthreads();
    if (warp == 0) {
        float x = (lane < 8) ? red[lane] : -1e30f;
        x = wmax(x);
        if (lane == 0) red[0] = x;
    }
    __syncthreads();
    mx = red[0];
    __syncthreads();

    float sum = 0.0f;
    #pragma unroll
    for (int i = 0; i < 5; i++) {
        int t = tid + i * 256;
        if (t < TT) { float e = expf(v[i] - mx); v[i] = e; sum += e; }
    }
    sum = wsum(sum);
    if (lane == 0) red[warp] = sum;
    __syncthreads();
    if (warp == 0) {
        float x = (lane < 8) ? red[lane] : 0.0f;
        x = wsum(x);
        if (lane == 0) red[0] = x;
    }
    __syncthreads();
    const float inv = 1.0f / red[0];

    #pragma unroll
    for (int i = 0; i < 5; i++) {
        int t = tid + i * 256;
        if (t < TT) {
            float p = v[i] * inv;
            __nv_bfloat16 hh, ll;
            bsplit(p, hh, ll);
            Phi[base + t] = hh;
            Plo[base + t] = ll;
        } else if (t < TP) {
            Phi[base + t] = __float2bfloat16(0.0f);
            Plo[base + t] = __float2bfloat16(0.0f);
        }
    }
}

// ---------------- launch ----------------
extern "C" void kernel_launch(void* const* d_in, const int* in_sizes, int n_in,
                              void* d_out, int out_size)
{
    const float* x    = (const float*)d_in[0];
    const float* mask = (const float*)d_in[1];
    const float* mem  = (const float*)d_in[2];
    const float* wq   = (const float*)d_in[3];
    const float* bq   = (const float*)d_in[4];
    const float* wk   = (const float*)d_in[5];
    const float* bk   = (const float*)d_in[6];
    const float* wv   = (const float*)d_in[7];
    const float* bv   = (const float*)d_in[8];
    const float* wo   = (const float*)d_in[9];
    const float* bo   = (const float*)d_in[10];
    float* out = (float*)d_out;

    __nv_bfloat16 *kvhi, *kvlo, *qhi, *qlo, *khi, *klo, *vthi, *vtlo, *phi, *plo, *hhi, *hlo;
    __nv_bfloat16 (*whi)[(size_t)DD * DD];
    __nv_bfloat16 (*wlo)[(size_t)DD * DD];
    float* sc;
    cudaGetSymbolAddress((void**)&kvhi, g_kvhi);
    cudaGetSymbolAddress((void**)&kvlo, g_kvlo);
    cudaGetSymbolAddress((void**)&qhi,  g_qhi);
    cudaGetSymbolAddress((void**)&qlo,  g_qlo);
    cudaGetSymbolAddress((void**)&khi,  g_khi);
    cudaGetSymbolAddress((void**)&klo,  g_klo);
    cudaGetSymbolAddress((void**)&vthi, g_vthi);
    cudaGetSymbolAddress((void**)&vtlo, g_vtlo);
    cudaGetSymbolAddress((void**)&sc,   g_sc);
    cudaGetSymbolAddress((void**)&phi,  g_phi);
    cudaGetSymbolAddress((void**)&plo,  g_plo);
    cudaGetSymbolAddress((void**)&hhi,  g_hhi);
    cudaGetSymbolAddress((void**)&hlo,  g_hlo);
    cudaGetSymbolAddress((void**)&whi,  g_whi);
    cudaGetSymbolAddress((void**)&wlo,  g_wlo);

    cudaFuncSetAttribute(gemm3, cudaFuncAttributeMaxDynamicSharedMemorySize, GSMEM);

    // 0: concat + split kv input
    {
        int n4 = NKV * (DD / 4);
        build_kv<<<(n4 + 255) / 256, 256>>>((const float4*)x, (const float4*)mem);
    }
    // 1: split all weights
    {
        int tot = 4 * (DD * DD / 4);
        split_all<<<(tot + 255) / 256, 256>>>((const float4*)wq, (const float4*)wk,
                                              (const float4*)wv, (const float4*)wo);
    }

    // 2: Q = x * wq^T + bq
    gemm3<<<dim3(DD / 128, SS / 256, BB), 256, GSMEM>>>(
        kvhi, kvlo, (long long)TT * DD, DD, SS,
        whi[0], wlo[0], 0, DD, DD,
        DD, 1.0f, bq, 1, nullptr, 0, 0,
        nullptr, qhi, qlo, (long long)SS * DD, DD);

    // 3: K = kv * wk^T + bk
    gemm3<<<dim3(DD / 128, NKV / 256, 1), 256, GSMEM>>>(
        kvhi, kvlo, 0, DD, NKV,
        whi[1], wlo[1], 0, DD, DD,
        DD, 1.0f, bk, 1, nullptr, 0, 0,
        nullptr, khi, klo, 0, DD);

    // 4: Vt[b] = wv * kv[b]^T + bv(rows)   [768 x TP]
    gemm3<<<dim3(TP / 128, DD / 256, BB), 256, GSMEM>>>(
        whi[2], wlo[2], 0, DD, DD,
        kvhi, kvlo, (long long)TT * DD, DD, TT,
        DD, 1.0f, bv, 2, nullptr, 0, 0,
        nullptr, vthi, vtlo, (long long)DD * TP, TP);

    // 5: scores[b] = SCALE * Q[b] K[b]^T + mask -> fp32
    gemm3<<<dim3(TP / 128, SS / 256, BB), 256, GSMEM>>>(
        qhi, qlo, (long long)SS * DD, DD, SS,
        khi, klo, (long long)TT * DD, DD, TT,
        DD, SCALE, nullptr, 0, mask, TT, TT,
        sc, nullptr, nullptr, (long long)SS * TP, TP);

    // 6: softmax -> split P (pad cols zeroed)
    softmax_split<<<NQ, 256>>>(sc, phi, plo);

    // 7: H[b] = P[b] * Vt[b]^T   (K trimmed to KPV=1056; P pad zeros cover rest)
    gemm3<<<dim3(DD / 128, SS / 256, BB), 256, GSMEM>>>(
        phi, plo, (long long)SS * TP, TP, SS,
        vthi, vtlo, (long long)DD * TP, TP, DD,
        KPV, 1.0f, nullptr, 0, nullptr, 0, 0,
        nullptr, hhi, hlo, (long long)SS * DD, DD);

    // 8: out = H * wo^T + bo -> fp32 d_out
    gemm3<<<dim3(DD / 128, NQ / 256, 1), 256, GSMEM>>>(
        hhi, hlo, 0, DD, NQ,
        whi[3], wlo[3], 0, DD, DD,
        DD, 1.0f, bo, 1, nullptr, 0, 0,
        out, nullptr, nullptr, 0, DD);
}